// round 9
// baseline (speedup 1.0000x reference)
#include <cuda_runtime.h>
#include <cstdint>
#include <math.h>

#define T_TOK 2048
#define DDIM  1024
#define NEXP  64
#define TOPK  8
#define FDIM  768
#define CAP   512

// -------------------- device scratch --------------------
__device__ int   g_cnt[NEXP];
__device__ int   g_slot_tok[NEXP * CAP];
__device__ float g_slot_w[NEXP * CAP];
__device__ float g_H[(size_t)NEXP * CAP * FDIM];        // ~100.7 MB
__device__ float g_shared_h[(size_t)T_TOK * FDIM];      // ~6.3 MB

// -------------------- helpers --------------------
__device__ __forceinline__ uint32_t f2tf32(float x) {
    uint32_t r;
    asm("cvt.rna.tf32.f32 %0, %1;" : "=r"(r) : "f"(x));
    return r;
}

__device__ __forceinline__ void cvt_store4r(float* dst, float4 v) {
    uint4 o;
    o.x = f2tf32(v.x); o.y = f2tf32(v.y); o.z = f2tf32(v.z); o.w = f2tf32(v.w);
    *reinterpret_cast<uint4*>(dst) = o;
}

__device__ __forceinline__ void mma8(float c[4], const uint32_t a[4],
                                     uint32_t b0, uint32_t b1) {
    asm volatile(
        "mma.sync.aligned.m16n8k8.row.col.f32.tf32.tf32.f32 "
        "{%0,%1,%2,%3},{%4,%5,%6,%7},{%8,%9},{%0,%1,%2,%3};\n"
        : "+f"(c[0]), "+f"(c[1]), "+f"(c[2]), "+f"(c[3])
        : "r"(a[0]), "r"(a[1]), "r"(a[2]), "r"(a[3]), "r"(b0), "r"(b1));
}

// B smem layout: [n][k-paired], pad 40 words/row, XOR swizzle on k-position by n.
// word(n,k) = n*40 + ((8*(k>>3) + 2*(k&3) + ((k>>2)&1)) ^ (8*((n>>2)&3)))
#define BPAD 40
#define BSZ  (128 * BPAD)   // 5120 words per B matrix

// -------------------- counters / output reset --------------------
__global__ void zero_cnt_kernel() {
    if (threadIdx.x < NEXP) g_cnt[threadIdx.x] = 0;
}
__global__ void zero_out_kernel(float4* out) {
    out[blockIdx.x * 256 + threadIdx.x] = make_float4(0.f, 0.f, 0.f, 0.f);
}

// -------------------- router --------------------
__global__ __launch_bounds__(256)
void router_kernel(const float* __restrict__ X, const float* __restrict__ RW) {
    __shared__ float xs[32][68];
    __shared__ float rws[64][68];
    __shared__ float probs[32][65];

    const int tid = threadIdx.x;
    const int t0  = blockIdx.x * 32;
    const int t   = tid >> 3;
    const int el  = tid & 7;

    float acc[8] = {0.f,0.f,0.f,0.f,0.f,0.f,0.f,0.f};

    for (int kc = 0; kc < DDIM; kc += 64) {
        #pragma unroll
        for (int i = 0; i < 2; i++) {
            int idx = tid + i * 256;
            int row = idx >> 4, c4 = idx & 15;
            *reinterpret_cast<float4*>(&xs[row][c4 * 4]) =
                *reinterpret_cast<const float4*>(X + (size_t)(t0 + row) * DDIM + kc + c4 * 4);
        }
        #pragma unroll
        for (int i = 0; i < 4; i++) {
            int idx = tid + i * 256;
            int row = idx >> 4, c4 = idx & 15;
            *reinterpret_cast<float4*>(&rws[row][c4 * 4]) =
                *reinterpret_cast<const float4*>(RW + (size_t)row * DDIM + kc + c4 * 4);
        }
        __syncthreads();
        for (int k = 0; k < 64; k++) {
            float xv = xs[t][k];
            #pragma unroll
            for (int j = 0; j < 8; j++) acc[j] += xv * rws[el + 8 * j][k];
        }
        __syncthreads();
    }

    float mx = acc[0];
    #pragma unroll
    for (int j = 1; j < 8; j++) mx = fmaxf(mx, acc[j]);
    #pragma unroll
    for (int m = 1; m < 8; m <<= 1) mx = fmaxf(mx, __shfl_xor_sync(0xffffffffu, mx, m));
    float p[8], s = 0.f;
    #pragma unroll
    for (int j = 0; j < 8; j++) { p[j] = expf(acc[j] - mx); s += p[j]; }
    #pragma unroll
    for (int m = 1; m < 8; m <<= 1) s += __shfl_xor_sync(0xffffffffu, s, m);
    float inv = 1.f / s;
    #pragma unroll
    for (int j = 0; j < 8; j++) probs[t][el + 8 * j] = p[j] * inv;
    __syncthreads();

    if (tid < 32) {
        const int token = t0 + tid;
        float tw[TOPK]; int te[TOPK];
        float psum = 0.f;
        #pragma unroll
        for (int k = 0; k < TOPK; k++) {
            float best = -1.f; int be = 0;
            for (int e2 = 0; e2 < NEXP; e2++) {
                float v = probs[tid][e2];
                if (v > best) { best = v; be = e2; }
            }
            probs[tid][be] = -2.f;
            tw[k] = best; te[k] = be; psum += best;
        }
        float invp = 1.f / psum;
        #pragma unroll
        for (int k = 0; k < TOPK; k++) {
            int pos = atomicAdd(&g_cnt[te[k]], 1);
            if (pos < CAP) {
                g_slot_tok[te[k] * CAP + pos] = token;
                g_slot_w[te[k] * CAP + pos]   = tw[k] * invp;
            }
        }
    }
}

// ==================== fused gate/up GEMM + SiLU (merged shared+experts) ====================
// BM=128, BN=128, BK=32, 512 threads. Pipelined LDG -> compute -> STS -> sync.
// Buffer: A 128*36=4608 + Bg 5120 + Bu 5120 = 14848 words; x2 buffers.
__global__ __launch_bounds__(512)
void gateup_kernel(const float* __restrict__ X, const float* __restrict__ WG,
                   const float* __restrict__ WU, const float* __restrict__ WSG) {
    extern __shared__ float smem[];
    float* bufs = smem;
    int* s_tok = (int*)(smem + 2 * 14848);

    const int tid = threadIdx.x;
    const int z   = blockIdx.z;
    const bool expert = (z < NEXP);
    const int e  = expert ? z : 0;
    const int ne = expert ? min(g_cnt[e], CAP) : T_TOK;
    const int m0 = expert ? blockIdx.y * 128 : ((z - NEXP) * 4 + blockIdx.y) * 128;
    if (m0 >= ne) return;
    const int n0 = blockIdx.x * 128;
    const int ldb = expert ? FDIM : 2 * FDIM;

    const float* Bg = expert ? (WG + (size_t)e * DDIM * FDIM) : WSG;
    const float* Bu = expert ? (WU + (size_t)e * DDIM * FDIM) : (WSG + FDIM);

    if (expert) {
        for (int i = tid; i < 128; i += 512) {
            int m = m0 + i;
            s_tok[i] = (m < ne) ? g_slot_tok[e * CAP + m] : 0;
        }
        __syncthreads();
    }

    // ---- producer coordinates ----
    // A: idx = tid + i*512 -> row = idx>>3, q = idx&7 (float4 along k)
    const float* rpA[2];
    int arow[2], ac4[2];
    #pragma unroll
    for (int i = 0; i < 2; i++) {
        int idx = tid + i * 512;
        arow[i] = idx >> 3; ac4[i] = idx & 7;
        rpA[i] = expert ? (X + (size_t)s_tok[arow[i]] * DDIM)
                        : (X + (size_t)(m0 + arow[i]) * DDIM);
    }
    // B: warp w, lane l: kk=l>>2 (k-row), n4=l&3. k = 8*(w&3)+kk ; n_i = 64i+16*(w>>2)+4*n4
    const int bw = tid >> 5, bl = tid & 31;
    const int bkk = bl >> 2, bn4 = bl & 3;
    const int bk  = 8 * (bw & 3) + bkk;
    const int qB  = (8 * (bw & 3) + 2 * (bkk & 3) + (bkk >> 2)) ^ (8 * bn4);
    int bnw[2];
    #pragma unroll
    for (int i = 0; i < 2; i++)
        bnw[i] = (64 * i + 16 * (bw >> 2) + 4 * bn4) * BPAD;
    const int bnoff0 = 16 * (bw >> 2) + 4 * bn4;   // n offset (without 64i)

    const int lane = tid & 31, warp = tid >> 5;
    const int wm = (warp >> 2) * 32, wn = (warp & 3) * 32;
    const int g = lane >> 2, tig = lane & 3;

    // consumer B fragment offsets
    int bB[4], xo[4];
    #pragma unroll
    for (int nf = 0; nf < 4; nf++) {
        bB[nf] = (wn + nf * 8 + g) * BPAD + 2 * tig;
        xo[nf] = 8 * ((2 * nf + (g >> 2)) & 3);
    }

    float cG[2][4][4] = {};
    float cU[2][4][4] = {};

    float4 hA[2], hBg[2], hBu[2];

    // ---- prologue: tile 0 ----
    #pragma unroll
    for (int i = 0; i < 2; i++) {
        hA[i]  = *reinterpret_cast<const float4*>(rpA[i] + ac4[i] * 4);
        size_t go = (size_t)bk * ldb + n0 + 64 * i + bnoff0;
        hBg[i] = *reinterpret_cast<const float4*>(Bg + go);
        hBu[i] = *reinterpret_cast<const float4*>(Bu + go);
    }
    {
        float* sA  = bufs;
        uint32_t* sBg = (uint32_t*)(sA + 4608);
        uint32_t* sBu = sBg + BSZ;
        #pragma unroll
        for (int i = 0; i < 2; i++) {
            cvt_store4r(&sA[arow[i] * 36 + ac4[i] * 4], hA[i]);
            const float* vg = (const float*)&hBg[i];
            const float* vu = (const float*)&hBu[i];
            #pragma unroll
            for (int t = 0; t < 4; t++) {
                sBg[bnw[i] + t * BPAD + qB] = f2tf32(vg[t]);
                sBu[bnw[i] + t * BPAD + qB] = f2tf32(vu[t]);
            }
        }
    }
    __syncthreads();

    const int NK = DDIM / 32;
    #pragma unroll 2
    for (int kt = 0; kt < NK; kt++) {
        if (kt + 1 < NK) {
            const int k1 = (kt + 1) * 32;
            #pragma unroll
            for (int i = 0; i < 2; i++) {
                hA[i] = *reinterpret_cast<const float4*>(rpA[i] + k1 + ac4[i] * 4);
                size_t go = (size_t)(k1 + bk) * ldb + n0 + 64 * i + bnoff0;
                hBg[i] = *reinterpret_cast<const float4*>(Bg + go);
                hBu[i] = *reinterpret_cast<const float4*>(Bu + go);
            }
        }

        {
            const uint32_t* uA = (const uint32_t*)(bufs + (kt & 1) * 14848);
            const uint32_t* uB = uA + 4608;      // gate; up at +BSZ
            #pragma unroll
            for (int ks = 0; ks < 4; ks++) {
                int ko = ks * 8;
                uint32_t a[2][4];
                #pragma unroll
                for (int mf = 0; mf < 2; mf++) {
                    int r = wm + mf * 16 + g;
                    a[mf][0] = uA[r * 36 + ko + tig];
                    a[mf][1] = uA[(r + 8) * 36 + ko + tig];
                    a[mf][2] = uA[r * 36 + ko + tig + 4];
                    a[mf][3] = uA[(r + 8) * 36 + ko + tig + 4];
                }
                #pragma unroll
                for (int nf = 0; nf < 4; nf++) {
                    int off = bB[nf] + (ko ^ xo[nf]);
                    uint2 bg = *reinterpret_cast<const uint2*>(uB + off);
                    uint2 bu = *reinterpret_cast<const uint2*>(uB + BSZ + off);
                    mma8(cG[0][nf], a[0], bg.x, bg.y);
                    mma8(cG[1][nf], a[1], bg.x, bg.y);
                    mma8(cU[0][nf], a[0], bu.x, bu.y);
                    mma8(cU[1][nf], a[1], bu.x, bu.y);
                }
            }
        }

        if (kt + 1 < NK) {
            float* sA  = bufs + ((kt + 1) & 1) * 14848;
            uint32_t* sBg = (uint32_t*)(sA + 4608);
            uint32_t* sBu = sBg + BSZ;
            #pragma unroll
            for (int i = 0; i < 2; i++) {
                cvt_store4r(&sA[arow[i] * 36 + ac4[i] * 4], hA[i]);
                const float* vg = (const float*)&hBg[i];
                const float* vu = (const float*)&hBu[i];
                #pragma unroll
                for (int t = 0; t < 4; t++) {
                    sBg[bnw[i] + t * BPAD + qB] = f2tf32(vg[t]);
                    sBu[bnw[i] + t * BPAD + qB] = f2tf32(vu[t]);
                }
            }
        }
        __syncthreads();
    }

    float* Hbase = expert ? (g_H + (size_t)e * CAP * FDIM) : g_shared_h;
    #pragma unroll
    for (int mf = 0; mf < 2; mf++)
        #pragma unroll
        for (int nf = 0; nf < 4; nf++)
            #pragma unroll
            for (int half = 0; half < 2; half++) {
                int row = wm + mf * 16 + g + half * 8;
                int col = wn + nf * 8 + 2 * tig;
                int m = m0 + row;
                if (m < ne) {
                    float g0 = cG[mf][nf][half * 2],     u0 = cU[mf][nf][half * 2];
                    float g1 = cG[mf][nf][half * 2 + 1], u1 = cU[mf][nf][half * 2 + 1];
                    float2 o;
                    o.x = g0 / (1.f + expf(-g0)) * u0;
                    o.y = g1 / (1.f + expf(-g1)) * u1;
                    *reinterpret_cast<float2*>(Hbase + (size_t)m * FDIM + n0 + col) = o;
                }
            }
}

// ==================== down GEMM (merged shared+experts, atomic add) ====================
// Buffer: A 4608 + B 5120 = 9728 words; x2 buffers. K = 768.
__global__ __launch_bounds__(512)
void down_kernel(const float* __restrict__ WD, const float* __restrict__ WSD,
                 float* __restrict__ out) {
    extern __shared__ float smem[];
    float* bufs = smem;
    int* s_tok = (int*)(smem + 2 * 9728);
    float* s_w = (float*)(s_tok + 128);

    const int tid = threadIdx.x;
    const int z   = blockIdx.z;
    const bool expert = (z < NEXP);
    const int e  = expert ? z : 0;
    const int ne = expert ? min(g_cnt[e], CAP) : T_TOK;
    const int m0 = expert ? blockIdx.y * 128 : ((z - NEXP) * 4 + blockIdx.y) * 128;
    if (m0 >= ne) return;
    const int n0 = blockIdx.x * 128;

    const float* B = expert ? (WD + (size_t)e * FDIM * DDIM) : WSD;
    const float* Abase = expert ? (g_H + (size_t)e * CAP * FDIM) : g_shared_h;

    if (expert) {
        for (int i = tid; i < 128; i += 512) {
            int m = m0 + i;
            s_tok[i] = (m < ne) ? g_slot_tok[e * CAP + m] : 0;
            s_w[i]   = (m < ne) ? g_slot_w[e * CAP + m] : 0.f;
        }
        __syncthreads();
    }

    int arow[2], ac4[2];
    #pragma unroll
    for (int i = 0; i < 2; i++) {
        int idx = tid + i * 512;
        arow[i] = idx >> 3; ac4[i] = idx & 7;
    }
    const int bw = tid >> 5, bl = tid & 31;
    const int bkk = bl >> 2, bn4 = bl & 3;
    const int bk  = 8 * (bw & 3) + bkk;
    const int qB  = (8 * (bw & 3) + 2 * (bkk & 3) + (bkk >> 2)) ^ (8 * bn4);
    int bnw[2];
    #pragma unroll
    for (int i = 0; i < 2; i++)
        bnw[i] = (64 * i + 16 * (bw >> 2) + 4 * bn4) * BPAD;
    const int bnoff0 = 16 * (bw >> 2) + 4 * bn4;

    const int lane = tid & 31, warp = tid >> 5;
    const int wm = (warp >> 2) * 32, wn = (warp & 3) * 32;
    const int g = lane >> 2, tig = lane & 3;

    int bB[4], xo[4];
    #pragma unroll
    for (int nf = 0; nf < 4; nf++) {
        bB[nf] = (wn + nf * 8 + g) * BPAD + 2 * tig;
        xo[nf] = 8 * ((2 * nf + (g >> 2)) & 3);
    }

    float c[2][4][4] = {};
    float4 hA[2], hB[2];

    #pragma unroll
    for (int i = 0; i < 2; i++) {
        hA[i] = *reinterpret_cast<const float4*>(Abase + (size_t)(m0 + arow[i]) * FDIM + ac4[i] * 4);
        hB[i] = *reinterpret_cast<const float4*>(B + (size_t)bk * DDIM + n0 + 64 * i + bnoff0);
    }
    {
        float* sA = bufs;
        uint32_t* sB = (uint32_t*)(sA + 4608);
        #pragma unroll
        for (int i = 0; i < 2; i++) {
            cvt_store4r(&sA[arow[i] * 36 + ac4[i] * 4], hA[i]);
            const float* vb = (const float*)&hB[i];
            #pragma unroll
            for (int t = 0; t < 4; t++)
                sB[bnw[i] + t * BPAD + qB] = f2tf32(vb[t]);
        }
    }
    __syncthreads();

    const int NK = FDIM / 32;
    #pragma unroll 2
    for (int kt = 0; kt < NK; kt++) {
        if (kt + 1 < NK) {
            const int k1 = (kt + 1) * 32;
            #pragma unroll
            for (int i = 0; i < 2; i++) {
                hA[i] = *reinterpret_cast<const float4*>(Abase + (size_t)(m0 + arow[i]) * FDIM + k1 + ac4[i] * 4);
                hB[i] = *reinterpret_cast<const float4*>(B + (size_t)(k1 + bk) * DDIM + n0 + 64 * i + bnoff0);
            }
        }

        {
            const uint32_t* uA = (const uint32_t*)(bufs + (kt & 1) * 9728);
            const uint32_t* uB = uA + 4608;
            #pragma unroll
            for (int ks = 0; ks < 4; ks++) {
                int ko = ks * 8;
                uint32_t a[2][4];
                #pragma unroll
                for (int mf = 0; mf < 2; mf++) {
                    int r = wm + mf * 16 + g;
                    a[mf][0] = uA[r * 36 + ko + tig];
                    a[mf][1] = uA[(r + 8) * 36 + ko + tig];
                    a[mf][2] = uA[r * 36 + ko + tig + 4];
                    a[mf][3] = uA[(r + 8) * 36 + ko + tig + 4];
                }
                #pragma unroll
                for (int nf = 0; nf < 4; nf++) {
                    int off = bB[nf] + (ko ^ xo[nf]);
                    uint2 b = *reinterpret_cast<const uint2*>(uB + off);
                    mma8(c[0][nf], a[0], b.x, b.y);
                    mma8(c[1][nf], a[1], b.x, b.y);
                }
            }
        }

        if (kt + 1 < NK) {
            float* sA = bufs + ((kt + 1) & 1) * 9728;
            uint32_t* sB = (uint32_t*)(sA + 4608);
            #pragma unroll
            for (int i = 0; i < 2; i++) {
                cvt_store4r(&sA[arow[i] * 36 + ac4[i] * 4], hA[i]);
                const float* vb = (const float*)&hB[i];
                #pragma unroll
                for (int t = 0; t < 4; t++)
                    sB[bnw[i] + t * BPAD + qB] = f2tf32(vb[t]);
            }
        }
        __syncthreads();
    }

    #pragma unroll
    for (int mf = 0; mf < 2; mf++)
        #pragma unroll
        for (int nf = 0; nf < 4; nf++)
            #pragma unroll
            for (int half = 0; half < 2; half++) {
                int row = wm + mf * 16 + g + half * 8;
                int col = wn + nf * 8 + 2 * tig;
                int m = m0 + row;
                if (m < ne) {
                    float v0 = c[mf][nf][half * 2];
                    float v1 = c[mf][nf][half * 2 + 1];
                    int   tokr = expert ? s_tok[row] : m;
                    float w    = expert ? s_w[row] : 1.f;
                    float* p = out + (size_t)tokr * DDIM + n0 + col;
                    asm volatile("red.global.add.v2.f32 [%0], {%1,%2};"
                                 :: "l"(p), "f"(v0 * w), "f"(v1 * w) : "memory");
                }
            }
}

// -------------------- launch --------------------
extern "C" void kernel_launch(void* const* d_in, const int* in_sizes, int n_in,
                              void* d_out, int out_size) {
    const float* X   = (const float*)d_in[0];   // (B,S,D)
    const float* RW  = (const float*)d_in[1];   // (E,D)
    const float* WG  = (const float*)d_in[2];   // (E,D,F)
    const float* WU  = (const float*)d_in[3];   // (E,D,F)
    const float* WD  = (const float*)d_in[4];   // (E,F,D)
    const float* WSG = (const float*)d_in[5];   // (D, 2*SF)
    const float* WSD = (const float*)d_in[6];   // (SF, D)
    float* out = (float*)d_out;

    const int GUSM = (2 * 14848) * 4 + 128 * 4;   // 119296
    const int DSM  = (2 * 9728) * 4 + 128 * 8;    // 78848

    cudaFuncSetAttribute(gateup_kernel, cudaFuncAttributeMaxDynamicSharedMemorySize, GUSM);
    cudaFuncSetAttribute(down_kernel,   cudaFuncAttributeMaxDynamicSharedMemorySize, DSM);

    zero_cnt_kernel<<<1, 64>>>();
    zero_out_kernel<<<(T_TOK * DDIM / 4) / 256, 256>>>((float4*)out);
    router_kernel<<<T_TOK / 32, 256>>>(X, RW);

    // z in [0,64): experts ; z in [64,68): shared expert (16 m-tiles via (z-64)*4+y)
    gateup_kernel<<<dim3(FDIM / 128, 4, NEXP + 4), 512, GUSM>>>(X, WG, WU, WSG);
    down_kernel<<<dim3(DDIM / 128, 4, NEXP + 4), 512, DSM>>>(WD, WSD, out);
}